// round 1
// baseline (speedup 1.0000x reference)
#include <cuda_runtime.h>

#define CS 8
#define NBINS 8
#define IMG 224
#define HC (IMG / CS)              // 28 cells per dim
#define TILE 32                    // pixels per tile dim
#define CPT 4                      // cells per tile dim
#define GRIDT (IMG / TILE)         // 7 tiles per dim
#define FEAT (HC * HC * NBINS)     // 6272 features per image
#define GW (TILE + 2)              // 34 gray rows/cols (with halo)
#define GSTRIDE (TILE + 4)         // 36, padded stride

__device__ __forceinline__ int octant_bin(float gx, float gy) {
    // bin = floor(mod(atan2(gy,gx), 2pi) / (pi/4)), half-open bins [k*45, (k+1)*45)
    int bin;
    if (gy > 0.0f) {
        if (gx > 0.0f) bin = (gy < gx) ? 0 : 1;      // [0,90): boundary gy==gx -> 45deg -> bin 1
        else           bin = (gy > -gx) ? 2 : 3;     // [90,180): gx==0 -> 90 -> bin 2; gy==-gx -> 135 -> bin 3
    } else if (gy < 0.0f) {
        if (gx < 0.0f) bin = (-gy < -gx) ? 4 : 5;    // [180,270): |gy|==|gx| -> 225 -> bin 5
        else           bin = (gx < -gy) ? 6 : 7;     // [270,360): gx==0 -> 270 -> bin 6; gx==-gy -> 315 -> bin 7
    } else {
        bin = (gx >= 0.0f) ? 0 : 4;                  // atan2(+-0, x>=0)=0 -> bin0; atan2(+-0, x<0)=pi -> bin4
    }
    return bin;
}

__global__ __launch_bounds__(256, 4)
void hog_hist_kernel(const float* __restrict__ x,
                     const float* __restrict__ gauss,
                     const float* __restrict__ kx,
                     const float* __restrict__ ky,
                     float* __restrict__ out) {
    const int b  = blockIdx.z;
    const int tx = blockIdx.x;   // tile col
    const int ty = blockIdx.y;   // tile row
    const int tid  = threadIdx.x;
    const int warp = tid >> 5;
    const int lane = tid & 31;

    __shared__ float sgray[GW * GSTRIDE];
    __shared__ float sg[CS * CS];
    __shared__ float shist[CPT * CPT * NBINS];   // 128

    // Load 3x3 conv kernels into registers (broadcast, L1-cached)
    float kxr[9], kyr[9];
#pragma unroll
    for (int i = 0; i < 9; i++) { kxr[i] = kx[i]; kyr[i] = ky[i]; }

    if (tid < CS * CS) sg[tid] = gauss[tid];

    // Gray conversion with 1-px halo; zero padding outside the image
    const float* xb = x + (size_t)b * 3 * IMG * IMG;
    const int y0 = ty * TILE - 1;
    const int x0 = tx * TILE - 1;
    for (int i = tid; i < GW * GW; i += 256) {
        int r = i / GW, c = i - r * GW;
        int gy_ = y0 + r, gx_ = x0 + c;
        float v = 0.0f;
        if (gy_ >= 0 && gy_ < IMG && gx_ >= 0 && gx_ < IMG) {
            int off = gy_ * IMG + gx_;
            float r0 = xb[off];
            float g0 = xb[IMG * IMG + off];
            float b0 = xb[2 * IMG * IMG + off];
            v = 0.2989f * r0 + 0.587f * g0 + 0.114f * b0;
        }
        sgray[r * GSTRIDE + c] = v;
    }
    __syncthreads();

    // Each warp handles 2 cells; each lane handles 2 horizontally adjacent pixels per cell.
#pragma unroll
    for (int cidx = 0; cidx < 2; cidx++) {
        const int cell = warp * 2 + cidx;        // 0..15
        const int cr = cell >> 2, cc = cell & 3; // cell coords in tile
        const int pr  = lane >> 2;               // in-cell row 0..7
        const int pc0 = (lane & 3) * 2;          // in-cell col 0,2,4,6
        const int r = cr * CS + pr;              // tile-pixel row
        const int c = cc * CS + pc0;             // tile-pixel col

        // 3x4 window covering both pixels' 3x3 stencils (sgray is offset by +1 halo)
        float v[3][4];
#pragma unroll
        for (int i = 0; i < 3; i++)
#pragma unroll
            for (int j = 0; j < 4; j++)
                v[i][j] = sgray[(r + i) * GSTRIDE + (c + j)];

        float gx0 = 0.f, gy0 = 0.f, gx1 = 0.f, gy1 = 0.f;
#pragma unroll
        for (int i = 0; i < 3; i++)
#pragma unroll
            for (int j = 0; j < 3; j++) {
                float kxv = kxr[i * 3 + j], kyv = kyr[i * 3 + j];
                gx0 += v[i][j]     * kxv;
                gy0 += v[i][j]     * kyv;
                gx1 += v[i][j + 1] * kxv;
                gy1 += v[i][j + 1] * kyv;
            }

        float h[NBINS];
#pragma unroll
        for (int bb = 0; bb < NBINS; bb++) h[bb] = 0.0f;

        {
            float mag = sqrtf(gx0 * gx0 + gy0 * gy0 + 1e-6f);
            float w   = mag * sg[pr * CS + pc0];
            int bin   = octant_bin(gx0, gy0);
#pragma unroll
            for (int bb = 0; bb < NBINS; bb++) h[bb] += (bin == bb) ? w : 0.0f;
        }
        {
            float mag = sqrtf(gx1 * gx1 + gy1 * gy1 + 1e-6f);
            float w   = mag * sg[pr * CS + pc0 + 1];
            int bin   = octant_bin(gx1, gy1);
#pragma unroll
            for (int bb = 0; bb < NBINS; bb++) h[bb] += (bin == bb) ? w : 0.0f;
        }

        // Warp reduction: butterfly per bin; lane b keeps bin b's total.
        float sval = 0.0f;
#pragma unroll
        for (int bb = 0; bb < NBINS; bb++) {
            float s = h[bb];
#pragma unroll
            for (int o = 16; o > 0; o >>= 1)
                s += __shfl_xor_sync(0xffffffffu, s, o);
            if (lane == bb) sval = s;
        }
        if (lane < NBINS) shist[cell * NBINS + lane] = sval;
    }
    __syncthreads();

    // Write 16 cells x 8 bins to global (each cell owned by exactly this block)
    float* ob = out + (size_t)b * FEAT;
    if (tid < CPT * CPT * NBINS) {
        int cell = tid >> 3, bin = tid & 7;
        int cy = ty * CPT + (cell >> 2);
        int cx = tx * CPT + (cell & 3);
        ob[(cy * HC + cx) * NBINS + bin] = shist[tid];
    }
}

__global__ __launch_bounds__(256)
void l2norm_kernel(float* __restrict__ out) {
    const int b = blockIdx.x;
    float* ob = out + (size_t)b * FEAT;
    const int tid = threadIdx.x;

    float s = 0.0f;
    for (int i = tid; i < FEAT; i += 256) {
        float v = ob[i];
        s += v * v;
    }
    __shared__ float red[8];
#pragma unroll
    for (int o = 16; o > 0; o >>= 1) s += __shfl_down_sync(0xffffffffu, s, o);
    if ((tid & 31) == 0) red[tid >> 5] = s;
    __syncthreads();
    if (tid < 32) {
        float v = (tid < 8) ? red[tid] : 0.0f;
#pragma unroll
        for (int o = 4; o > 0; o >>= 1) v += __shfl_down_sync(0xffffffffu, v, o);
        if (tid == 0) red[0] = v;
    }
    __syncthreads();
    const float inv = 1.0f / (sqrtf(red[0]) + 1e-6f);
    for (int i = tid; i < FEAT; i += 256) ob[i] *= inv;
}

extern "C" void kernel_launch(void* const* d_in, const int* in_sizes, int n_in,
                              void* d_out, int out_size) {
    const float* x     = (const float*)d_in[0];
    const float* gauss = (const float*)d_in[1];
    const float* kx    = (const float*)d_in[2];
    const float* ky    = (const float*)d_in[3];
    float* out = (float*)d_out;

    const int bs = in_sizes[0] / (3 * IMG * IMG);

    dim3 grid(GRIDT, GRIDT, bs);
    hog_hist_kernel<<<grid, 256>>>(x, gauss, kx, ky, out);
    l2norm_kernel<<<bs, 256>>>(out);
}